// round 7
// baseline (speedup 1.0000x reference)
#include <cuda_runtime.h>
#include <math.h>

// ---------------------------------------------------------------------------
// Problem constants
// ---------------------------------------------------------------------------
constexpr int BB = 32;      // batch
constexpr int NS = 128;     // slots
constexpr int NF = 4096;    // features
constexpr int DD = 256;     // slot dim
constexpr int HH = 1024;    // mlp hidden

// ---------------------------------------------------------------------------
// Device scratch (static globals: allocation-free, graph-safe)
// ---------------------------------------------------------------------------
__device__ float g_h[4][64];                       // per-head time-MLP hidden
__device__ float g_W[983040];                      // Wq | Wg | Wf0 | Wf1 (row-major [dout,din])
__device__ float g_catA[(size_t)BB * NS * 2 * DD]; // [lnA(slots) , f_attn]
__device__ float g_catF[(size_t)BB * NS * 2 * DD]; // [lnF(slots) , f_attn]
__device__ float g_q[(size_t)BB * NS * DD];
__device__ float g_L[(size_t)BB * NS * NF];        // logits, then probabilities (in-place)
__device__ float g_cmax[(size_t)BB * NF];
__device__ float g_csum[(size_t)BB * NF];
__device__ float g_S[(size_t)BB * NS];
__device__ float g_ffh[(size_t)BB * NS * HH];

// W offsets inside g_W
constexpr int OFF_WQ  = 0;          // 256*256
constexpr int OFF_WG  = 65536;      // 256*512
constexpr int OFF_WF0 = 196608;     // 1024*512
constexpr int OFF_WF1 = 720896;     // 256*1024

// ---------------------------------------------------------------------------
// Helpers
// ---------------------------------------------------------------------------
__device__ __forceinline__ float block_sum(float v, float* red) {
    __syncthreads();                       // allow helper reuse of red[]
    int lane = threadIdx.x & 31, w = threadIdx.x >> 5;
    #pragma unroll
    for (int o = 16; o; o >>= 1) v += __shfl_xor_sync(0xffffffffu, v, o);
    if (lane == 0) red[w] = v;
    __syncthreads();
    float tot = 0.f;
    int nw = (blockDim.x + 31) >> 5;
    for (int i = 0; i < nw; i++) tot += red[i];
    return tot;
}

// ---------------------------------------------------------------------------
// Kernel 1: sinusoidal embedding + 2-layer SiLU MLP for all 4 heads
// grid = 4 (head), block = 64
// ---------------------------------------------------------------------------
__global__ void time_mlp_kernel(
    const float* __restrict__ t_ptr,
    const float* qw0, const float* qb0, const float* qw1, const float* qb1,
    const float* gw0, const float* gb0, const float* gw1, const float* gb1,
    const float* f0w0, const float* f0b0, const float* f0w1, const float* f0b1,
    const float* f1w0, const float* f1b0, const float* f1w1, const float* f1b1)
{
    const float* w0s[4] = {qw0, gw0, f0w0, f1w0};
    const float* b0s[4] = {qb0, gb0, f0b0, f1b0};
    const float* w1s[4] = {qw1, gw1, f0w1, f1w1};
    const float* b1s[4] = {qb1, gb1, f0b1, f1b1};
    int head = blockIdx.x;
    const float* w0 = w0s[head]; const float* b0 = b0s[head];
    const float* w1 = w1s[head]; const float* b1 = b1s[head];

    __shared__ float emb[257];
    __shared__ float h0[64];
    int tid = threadIdx.x;
    float t = t_ptr[0];
    if (tid == 0) emb[0] = t;
    const float fscale = -logf(10000.0f) / 128.0f;
    #pragma unroll
    for (int i = tid; i < 128; i += 64) {
        float w = fscale * (float)i * t;
        emb[1 + i]   = sinf(w);
        emb[129 + i] = cosf(w);
    }
    __syncthreads();
    float s = b0[tid];
    for (int j = 0; j < 257; j++) s += w0[tid * 257 + j] * emb[j];
    h0[tid] = s / (1.f + expf(-s));          // silu
    __syncthreads();
    float s2 = b1[tid];
    #pragma unroll 8
    for (int j = 0; j < 64; j++) s2 += w1[tid * 64 + j] * h0[j];
    g_h[head][tid] = s2 / (1.f + expf(-s2)); // silu
}

// ---------------------------------------------------------------------------
// Kernel 2: W = wp @ h + bp for all heads (983040 rows x 64) -> g_W
// grid = 3840, block = 256
// ---------------------------------------------------------------------------
__global__ __launch_bounds__(256) void wproj_kernel(
    const float* __restrict__ qwp,  const float* __restrict__ qbp,
    const float* __restrict__ gwp,  const float* __restrict__ gbp,
    const float* __restrict__ f0wp, const float* __restrict__ f0bp,
    const float* __restrict__ f1wp, const float* __restrict__ f1bp)
{
    long long r = (long long)blockIdx.x * 256 + threadIdx.x;
    int head; const float* wp; const float* bp; long long lr;
    if (r < 65536)       { head = 0; wp = qwp;  bp = qbp;  lr = r; }
    else if (r < 196608) { head = 1; wp = gwp;  bp = gbp;  lr = r - 65536; }
    else if (r < 720896) { head = 2; wp = f0wp; bp = f0bp; lr = r - 196608; }
    else                 { head = 3; wp = f1wp; bp = f1bp; lr = r - 720896; }

    __shared__ float hs[64];
    if (threadIdx.x < 64) hs[threadIdx.x] = g_h[head][threadIdx.x]; // whole block same head
    __syncthreads();

    const float4* w4 = (const float4*)(wp + lr * 64);
    float s = bp[lr];
    #pragma unroll
    for (int j = 0; j < 16; j++) {
        float4 x = w4[j];
        s += x.x * hs[4 * j] + x.y * hs[4 * j + 1] + x.z * hs[4 * j + 2] + x.w * hs[4 * j + 3];
    }
    g_W[r] = s;
}

// ---------------------------------------------------------------------------
// Kernel 3: LayerNorm -> first halves of g_catA (lnA affine) / g_catF (lnF)
// grid = 4096 (b*n), block = 256
// ---------------------------------------------------------------------------
__global__ __launch_bounds__(256) void ln_kernel(
    const float* __restrict__ slots,
    const float* __restrict__ aw, const float* __restrict__ ab,
    const float* __restrict__ fw, const float* __restrict__ fb)
{
    __shared__ float red[8];
    long long row = blockIdx.x;
    int d = threadIdx.x;
    float x = slots[row * 256 + d];
    float mu  = block_sum(x, red) * (1.f / 256.f);
    float dv  = x - mu;
    float var = block_sum(dv * dv, red) * (1.f / 256.f);
    float xh  = dv * rsqrtf(var + 1e-5f);
    g_catA[row * 512 + d] = xh * aw[d] + ab[d];
    g_catF[row * 512 + d] = xh * fw[d] + fb[d];
}

// ---------------------------------------------------------------------------
// Generic tiled SGEMM: C[M,N] = epi(alpha * A[M,K] @ B[N,K]^T)
// EPI: 0 = store, 1 = relu, 2 = sigmoid(v)*faux -> C, 3 = C += v
// 256 threads. BMxBN tile, BK=8, TMxTN register tile.
// ---------------------------------------------------------------------------
template<int BM, int BN, int TM, int TN, int EPI>
__global__ __launch_bounds__(256) void gemm_tn(
    const float* __restrict__ A, int lda, long long sA,
    const float* __restrict__ B, int ldb, long long sB,
    float* __restrict__ C, int ldc, long long sC,
    int K, float alpha, const float* __restrict__ faux, int ldf)
{
    constexpr int BK = 8;
    static_assert((BM / TM) * (BN / TN) == 256, "256 threads");
    const int z = blockIdx.z;
    A += sA * z; B += sB * z; C += sC * z;

    __shared__ __align__(16) float As[BK][BM];
    __shared__ __align__(16) float Bs[BK][BN];

    const int t = threadIdx.x;
    const long long brow = (long long)blockIdx.y * BM;
    const int bcol = blockIdx.x * BN;

    constexpr int AVW  = (BM * BK) / 256;   // floats per thread for A tile (4 or 2)
    constexpr int ATPR = BK / AVW;
    const int alr = t / ATPR;
    const int alc = (t % ATPR) * AVW;
    constexpr int BVW  = (BN * BK) / 256;
    constexpr int BTPR = BK / BVW;
    const int blr = t / BTPR;
    const int blc = (t % BTPR) * BVW;

    const float* Ap = A + (brow + alr) * lda + alc;
    const float* Bp = B + (long long)(bcol + blr) * ldb + blc;

    const int tr = (t / (BN / TN)) * TM;
    const int tc = (t % (BN / TN)) * TN;

    float acc[TM][TN] = {};

    for (int k0 = 0; k0 < K; k0 += BK) {
        float ar[AVW], br[BVW];
        if constexpr (AVW == 4) {
            float4 v = *(const float4*)(Ap + k0);
            ar[0] = v.x; ar[1] = v.y; ar[2] = v.z; ar[3] = v.w;
        } else {
            float2 v = *(const float2*)(Ap + k0);
            ar[0] = v.x; ar[1] = v.y;
        }
        if constexpr (BVW == 4) {
            float4 v = *(const float4*)(Bp + k0);
            br[0] = v.x; br[1] = v.y; br[2] = v.z; br[3] = v.w;
        } else {
            float2 v = *(const float2*)(Bp + k0);
            br[0] = v.x; br[1] = v.y;
        }
        __syncthreads();
        #pragma unroll
        for (int u = 0; u < AVW; u++) As[alc + u][alr] = ar[u];
        #pragma unroll
        for (int u = 0; u < BVW; u++) Bs[blc + u][blr] = br[u];
        __syncthreads();

        #pragma unroll
        for (int kk = 0; kk < BK; kk++) {
            float a[TM], b[TN];
            #pragma unroll
            for (int i = 0; i < TM; i += 4)
                *(float4*)&a[i] = *(const float4*)&As[kk][tr + i];
            #pragma unroll
            for (int j = 0; j < TN; j += 4)
                *(float4*)&b[j] = *(const float4*)&Bs[kk][tc + j];
            #pragma unroll
            for (int i = 0; i < TM; i++)
                #pragma unroll
                for (int j = 0; j < TN; j++)
                    acc[i][j] = fmaf(a[i], b[j], acc[i][j]);
        }
    }

    #pragma unroll
    for (int i = 0; i < TM; i++) {
        long long r = brow + tr + i;
        float* Crow = C + r * ldc;
        #pragma unroll
        for (int j = 0; j < TN; j++) {
            int cix = bcol + tc + j;
            float v = acc[i][j] * alpha;
            if (EPI == 0)      Crow[cix] = v;
            else if (EPI == 1) Crow[cix] = fmaxf(v, 0.f);
            else if (EPI == 2) Crow[cix] = faux[r * (long long)ldf + cix] / (1.f + expf(-v));
            else               Crow[cix] += v;
        }
    }
}

// ---------------------------------------------------------------------------
// Kernel: column softmax stats (max & sum of exp over the 128 slots per column)
// grid = (32 colgroups, 32 batches), block = 128
// ---------------------------------------------------------------------------
__global__ __launch_bounds__(128) void colstats_kernel()
{
    int b = blockIdx.y;
    int m = blockIdx.x * 128 + threadIdx.x;
    const float* Lb = g_L + (long long)b * NS * NF;
    float mx = -3.4e38f, s = 0.f;
    for (int n = 0; n < NS; n++) {
        float x = Lb[(long long)n * NF + m];
        if (x > mx) { s = s * expf(mx - x) + 1.f; mx = x; }
        else        { s += expf(x - mx); }
    }
    g_cmax[(long long)b * NF + m] = mx;
    g_csum[(long long)b * NF + m] = s;
}

// ---------------------------------------------------------------------------
// Kernel: overwrite logits with probabilities p = exp(l - cmax)/csum,
// and compute per-row sum S.  grid = (128 rows, 32 batches), block = 256
// ---------------------------------------------------------------------------
__global__ __launch_bounds__(256) void rowsum_kernel()
{
    __shared__ float red[8];
    int b = blockIdx.y, n = blockIdx.x;
    float* Lr = g_L + ((long long)b * NS + n) * NF;
    const float* cm = g_cmax + (long long)b * NF;
    const float* cs = g_csum + (long long)b * NF;
    float s = 0.f;
    for (int m = threadIdx.x; m < NF; m += 256) {
        float p = expf(Lr[m] - cm[m]) / cs[m];
        Lr[m] = p;
        s += p;
    }
    float tot = block_sum(s, red);
    if (threadIdx.x == 0) g_S[b * NS + n] = tot;
}

// ---------------------------------------------------------------------------
// Kernel: f_attn = (P @ V) / (S + 1e-8) -> second halves of catA / catF
// grid = (4 d-tiles, 2 row-tiles, 32 batches), block = 256. 64x64 tile, BK=32.
// ---------------------------------------------------------------------------
__global__ __launch_bounds__(256) void pv_kernel(const float* __restrict__ V)
{
    int b  = blockIdx.z;
    int n0 = blockIdx.y * 64;
    int d0 = blockIdx.x * 64;
    const float* Pb = g_L + (long long)b * NS * NF + (long long)n0 * NF;
    const float* Vb = V + (long long)b * NF * DD;

    __shared__ __align__(16) float Ps[64][32];
    __shared__ __align__(16) float Vs[32][64];

    int t = threadIdx.x;
    int tr = (t >> 4) * 4;
    int tc = (t & 15) * 4;
    float acc[4][4] = {};

    for (int m0 = 0; m0 < NF; m0 += 32) {
        float4 p4[2], v4[2];
        #pragma unroll
        for (int u = 0; u < 2; u++) {
            int fid = t + u * 256;
            int n = fid >> 3, c = (fid & 7) * 4;
            p4[u] = *(const float4*)(Pb + (long long)n * NF + m0 + c);
            int m = fid >> 4, cv = (fid & 15) * 4;
            v4[u] = *(const float4*)(Vb + (long long)(m0 + m) * DD + d0 + cv);
        }
        __syncthreads();
        #pragma unroll
        for (int u = 0; u < 2; u++) {
            int fid = t + u * 256;
            int n = fid >> 3, c = (fid & 7) * 4;
            *(float4*)&Ps[n][c] = p4[u];
            int m = fid >> 4, cv = (fid & 15) * 4;
            *(float4*)&Vs[m][cv] = v4[u];
        }
        __syncthreads();
        #pragma unroll
        for (int kk = 0; kk < 32; kk++) {
            float bv[4];
            *(float4*)bv = *(const float4*)&Vs[kk][tc];
            #pragma unroll
            for (int i = 0; i < 4; i++) {
                float a = Ps[tr + i][kk];
                acc[i][0] = fmaf(a, bv[0], acc[i][0]);
                acc[i][1] = fmaf(a, bv[1], acc[i][1]);
                acc[i][2] = fmaf(a, bv[2], acc[i][2]);
                acc[i][3] = fmaf(a, bv[3], acc[i][3]);
            }
        }
    }

    #pragma unroll
    for (int i = 0; i < 4; i++) {
        int n = n0 + tr + i;
        float rs = 1.f / (g_S[b * NS + n] + 1e-8f);
        float4 o = make_float4(acc[i][0] * rs, acc[i][1] * rs, acc[i][2] * rs, acc[i][3] * rs);
        long long off = ((long long)b * NS + n) * 512 + 256 + d0 + tc;
        *(float4*)&g_catA[off] = o;
        *(float4*)&g_catF[off] = o;
    }
}

// ---------------------------------------------------------------------------
// Host launcher
// ---------------------------------------------------------------------------
extern "C" void kernel_launch(void* const* d_in, const int* in_sizes, int n_in,
                              void* d_out, int out_size)
{
    // Input ordering: either reference-signature order (t first, size 1)
    // or setup_inputs order (q_w0 first, size 16448).
    const bool tfirst = (in_sizes[0] == 1);
    const int iH  = tfirst ? 4  : 0;   // head params start
    const int iLn = tfirst ? 28 : 24;
    const int iT  = tfirst ? 0  : 28;
    const int iS  = tfirst ? 1  : 29;
    const int iK  = tfirst ? 2  : 30;
    const int iV  = tfirst ? 3  : 31;

    auto F = [&](int i) { return (const float*)d_in[i]; };
    const float* t     = F(iT);
    const float* slots = F(iS);
    const float* kin   = F(iK);
    const float* vin   = F(iV);

    const float *hw0[4], *hb0[4], *hw1[4], *hb1[4], *hwp[4], *hbp[4];
    for (int h = 0; h < 4; h++) {
        int base = iH + h * 6;
        hw0[h] = F(base);     hb0[h] = F(base + 1);
        hw1[h] = F(base + 2); hb1[h] = F(base + 3);
        hwp[h] = F(base + 4); hbp[h] = F(base + 5);
    }

    float *pW, *pcatA, *pcatF, *pq, *pL, *pffh;
    cudaGetSymbolAddress((void**)&pW,    g_W);
    cudaGetSymbolAddress((void**)&pcatA, g_catA);
    cudaGetSymbolAddress((void**)&pcatF, g_catF);
    cudaGetSymbolAddress((void**)&pq,    g_q);
    cudaGetSymbolAddress((void**)&pL,    g_L);
    cudaGetSymbolAddress((void**)&pffh,  g_ffh);

    float* out = (float*)d_out;

    // 1) time-dependent MLPs (tiny)
    time_mlp_kernel<<<4, 64>>>(t,
        hw0[0], hb0[0], hw1[0], hb1[0],
        hw0[1], hb0[1], hw1[1], hb1[1],
        hw0[2], hb0[2], hw1[2], hb1[2],
        hw0[3], hb0[3], hw1[3], hb1[3]);

    // 2) W = wp @ h + bp for all 4 heads (983040 rows)
    wproj_kernel<<<3840, 256>>>(hwp[0], hbp[0], hwp[1], hbp[1],
                                hwp[2], hbp[2], hwp[3], hbp[3]);

    // 3) LayerNorm -> catA/catF first halves
    ln_kernel<<<4096, 256>>>(slots, F(iLn), F(iLn + 1), F(iLn + 2), F(iLn + 3));

    // 4) q = lnA(slots) @ Wq^T      [4096,256]x[256,256]
    gemm_tn<64, 64, 4, 4, 0><<<dim3(4, 64, 1), 256>>>(
        pcatA, 512, 0, pW + OFF_WQ, 256, 0, pq, 256, 0, 256, 1.f, nullptr, 0);

    // 5) logits = scale * q @ k^T   per batch [128,256]x[4096,256]
    gemm_tn<128, 128, 8, 8, 0><<<dim3(32, 1, 32), 256>>>(
        pq, 256, (long long)NS * DD,
        kin, 256, (long long)NF * DD,
        pL, NF, (long long)NS * NF,
        256, 0.0625f, nullptr, 0);

    // 6) softmax over slots: per-column max & sum
    colstats_kernel<<<dim3(32, 32), 128>>>();

    // 7) overwrite L with probabilities; row sums S
    rowsum_kernel<<<dim3(128, 32), 256>>>();

    // 8) f_attn = (P @ V) / (S+1e-8) -> catA/catF second halves
    pv_kernel<<<dim3(4, 2, 32), 256>>>(vin);

    // 9) out = sigmoid(catA @ Wg^T) * f_attn
    gemm_tn<64, 64, 4, 4, 2><<<dim3(4, 64, 1), 256>>>(
        pcatA, 512, 0, pW + OFF_WG, 512, 0, out, 256, 0,
        512, 1.f, pcatA + 256, 512);

    // 10) h = relu(catF @ Wf0^T)    [4096,512]x[1024,512]
    gemm_tn<128, 128, 8, 8, 1><<<dim3(8, 32, 1), 256>>>(
        pcatF, 512, 0, pW + OFF_WF0, 512, 0, pffh, 1024, 0,
        512, 1.f, nullptr, 0);

    // 11) out += h @ Wf1^T
    gemm_tn<64, 64, 4, 4, 3><<<dim3(4, 64, 1), 256>>>(
        pffh, 1024, 0, pW + OFF_WF1, 1024, 0, out, 256, 0,
        1024, 1.f, nullptr, 0);
}